// round 2
// baseline (speedup 1.0000x reference)
#include <cuda_runtime.h>
#include <cuda_bf16.h>
#include <cstdint>

// ---------------------------------------------------------------------------
// CrossAttention: B=1, I=J=1024, C_S=1024, H=16, D=64, C_Z=128
// Round 2: fp32 baseline; fix misaligned STS.128 in zproj (129-stride smem).
// ---------------------------------------------------------------------------

#define NN 1024
#define HEADS 16
#define HD 64
#define CZ 128

// Scratch (device globals; allocation is forbidden)
__device__ float g_q [NN * NN];
__device__ float g_k [NN * NN];
__device__ float g_v [NN * NN];
__device__ float g_g [NN * NN];
__device__ float g_o [NN * NN];
__device__ float g_go[NN * NN];
__device__ float g_z [HEADS * NN * NN];   // logits / probs, 64 MB

// ---------------------------------------------------------------------------
// NT SGEMM: C[m,n] = alpha * sum_k A[m,k] * B[n,k]  (+Cin) (+bias[n]) (+act)
// BM=BN=128, BK=8, 8x8 per thread, 256 threads. Batched via blockIdx.z.
// ---------------------------------------------------------------------------
__global__ void __launch_bounds__(256)
sgemm_nt_128(const float* __restrict__ A, int lda, long long bsA,
             const float* __restrict__ B, int ldb, long long bsB,
             const float* __restrict__ bias,
             const float* __restrict__ Cin, long long bsCin,
             float* __restrict__ C, int ldc, long long bsC,
             int K, float alpha, int act)
{
    __shared__ float As[8][128];
    __shared__ float Bs[8][128];

    const int tid = threadIdx.x;
    const int bx = blockIdx.x, by = blockIdx.y, bz = blockIdx.z;

    const float* Ab = A + bz * bsA + (long long)by * 128 * lda;
    const float* Bb = B + bz * bsB + (long long)bx * 128 * ldb;

    const int lr = tid >> 1;        // 0..127 row for loads
    const int lk = (tid & 1) * 4;   // 0 or 4
    const int ct = tid & 15;        // compute col group
    const int rt = tid >> 4;        // compute row group

    float acc[8][8];
#pragma unroll
    for (int i = 0; i < 8; i++)
#pragma unroll
        for (int j = 0; j < 8; j++) acc[i][j] = 0.f;

    for (int k0 = 0; k0 < K; k0 += 8) {
        float4 av = *(const float4*)(Ab + (long long)lr * lda + k0 + lk);
        float4 bv = *(const float4*)(Bb + (long long)lr * ldb + k0 + lk);
        As[lk + 0][lr] = av.x; As[lk + 1][lr] = av.y;
        As[lk + 2][lr] = av.z; As[lk + 3][lr] = av.w;
        Bs[lk + 0][lr] = bv.x; Bs[lk + 1][lr] = bv.y;
        Bs[lk + 2][lr] = bv.z; Bs[lk + 3][lr] = bv.w;
        __syncthreads();
#pragma unroll
        for (int kk = 0; kk < 8; kk++) {
            float a[8], b[8];
#pragma unroll
            for (int i = 0; i < 8; i++) a[i] = As[kk][rt * 8 + i];
#pragma unroll
            for (int j = 0; j < 8; j++) b[j] = Bs[kk][ct * 8 + j];
#pragma unroll
            for (int i = 0; i < 8; i++)
#pragma unroll
                for (int j = 0; j < 8; j++) acc[i][j] += a[i] * b[j];
        }
        __syncthreads();
    }

    const float* CinB = Cin ? (Cin + bz * bsCin) : nullptr;
    float* CB = C + bz * bsC;
#pragma unroll
    for (int i = 0; i < 8; i++) {
        int m = by * 128 + rt * 8 + i;
#pragma unroll
        for (int j = 0; j < 8; j++) {
            int n = bx * 128 + ct * 8 + j;
            float v = alpha * acc[i][j];
            if (CinB) v += CinB[(long long)m * ldc + n];
            if (bias) v += bias[n];
            if (act == 1) v = 1.f / (1.f + __expf(-v));
            CB[(long long)m * ldc + n] = v;
        }
    }
}

// ---------------------------------------------------------------------------
// NN GEMM for O = P @ V : C[m,n] = sum_k A[m,k] * B[k,n]
// BM=128, BN=64, BK=8, 8x4 per thread, 256 threads. Batched over heads.
// ---------------------------------------------------------------------------
__global__ void __launch_bounds__(256)
sgemm_nn_128x64(const float* __restrict__ A, int lda, long long bsA,
                const float* __restrict__ B, int ldb, long long bsB,
                float* __restrict__ C, int ldc, long long bsC, int K)
{
    __shared__ float As[8][128];
    __shared__ float Bs[8][64];

    const int tid = threadIdx.x;
    const int by = blockIdx.y, bz = blockIdx.z;

    const float* Ab = A + bz * bsA + (long long)by * 128 * lda;
    const float* Bb = B + bz * bsB;

    const int lr = tid >> 1;
    const int lk = (tid & 1) * 4;
    const int bn = (2 * tid) & 63;   // B load: n index (even)
    const int bk = (2 * tid) >> 6;   // B load: k index
    const int ct = tid & 15;         // col group (4 cols each)
    const int rt = tid >> 4;         // row group (8 rows each)

    float acc[8][4];
#pragma unroll
    for (int i = 0; i < 8; i++)
#pragma unroll
        for (int j = 0; j < 4; j++) acc[i][j] = 0.f;

    for (int k0 = 0; k0 < K; k0 += 8) {
        float4 av = *(const float4*)(Ab + (long long)lr * lda + k0 + lk);
        As[lk + 0][lr] = av.x; As[lk + 1][lr] = av.y;
        As[lk + 2][lr] = av.z; As[lk + 3][lr] = av.w;
        float2 bv = *(const float2*)(Bb + (long long)(k0 + bk) * ldb + bn);
        Bs[bk][bn] = bv.x; Bs[bk][bn + 1] = bv.y;
        __syncthreads();
#pragma unroll
        for (int kk = 0; kk < 8; kk++) {
            float a[8], b[4];
#pragma unroll
            for (int i = 0; i < 8; i++) a[i] = As[kk][rt * 8 + i];
#pragma unroll
            for (int j = 0; j < 4; j++) b[j] = Bs[kk][ct * 4 + j];
#pragma unroll
            for (int i = 0; i < 8; i++)
#pragma unroll
                for (int j = 0; j < 4; j++) acc[i][j] += a[i] * b[j];
        }
        __syncthreads();
    }

    float* CB = C + bz * bsC;
#pragma unroll
    for (int i = 0; i < 8; i++) {
        int m = by * 128 + rt * 8 + i;
#pragma unroll
        for (int j = 0; j < 4; j++) {
            int n = ct * 4 + j;
            CB[(long long)m * ldc + n] = acc[i][j];
        }
    }
}

// ---------------------------------------------------------------------------
// z projection: z[h, p] = sum_c bias[p, c] * Wz[c, h] + (1-mask[j])*(-1e6)
// p = i*1024 + j flattened. 64 pairs per block, 128 threads (2 threads/pair).
// Global load is LDG.128 (coalesced); shared fill uses 4x STS.32 because the
// 129-float row stride (conflict-free reads) breaks 16B alignment for odd r.
// ---------------------------------------------------------------------------
__global__ void __launch_bounds__(128)
zproj_kernel(const float* __restrict__ bias, const float* __restrict__ Wz,
             const float* __restrict__ mask, float* __restrict__ z)
{
    __shared__ float bs[64][129];      // [pair][c], pad -> conflict-free reads
    __shared__ float wzs[128][16];     // [c][h]

    const int tid = threadIdx.x;
    const long long p0 = (long long)blockIdx.x * 64;

    for (int e = tid; e < CZ * HEADS; e += 128)
        wzs[e >> 4][e & 15] = Wz[e];

    const int c4 = tid & 31;
    const int r0 = tid >> 5;
#pragma unroll
    for (int r = r0; r < 64; r += 4) {
        float4 v = *(const float4*)(bias + (p0 + r) * CZ + c4 * 4);
        bs[r][c4 * 4 + 0] = v.x;
        bs[r][c4 * 4 + 1] = v.y;
        bs[r][c4 * 4 + 2] = v.z;
        bs[r][c4 * 4 + 3] = v.w;
    }
    __syncthreads();

    const int pair = tid & 63;
    const int hh = (tid >> 6) * 8;     // 0 or 8

    float acc[8];
#pragma unroll
    for (int h = 0; h < 8; h++) acc[h] = 0.f;

#pragma unroll 8
    for (int c = 0; c < CZ; c++) {
        float bv = bs[pair][c];
        float4 w0 = *(const float4*)&wzs[c][hh];
        float4 w1 = *(const float4*)&wzs[c][hh + 4];
        acc[0] += bv * w0.x; acc[1] += bv * w0.y;
        acc[2] += bv * w0.z; acc[3] += bv * w0.w;
        acc[4] += bv * w1.x; acc[5] += bv * w1.y;
        acc[6] += bv * w1.z; acc[7] += bv * w1.w;
    }

    const long long p = p0 + pair;
    const int j = (int)(p & (NN - 1));
    const float madd = (1.0f - mask[j]) * (-1000000.0f);
#pragma unroll
    for (int h = 0; h < 8; h++)
        z[(long long)(hh + h) * (NN * NN) + p] = acc[h] + madd;
}

// ---------------------------------------------------------------------------
// Row softmax over last dim (1024), in place. One block (256 thr) per row.
// ---------------------------------------------------------------------------
__global__ void __launch_bounds__(256)
softmax_kernel(float* __restrict__ z)
{
    float4* row = (float4*)(z + (long long)blockIdx.x * NN);
    const int tid = threadIdx.x;
    float4 v = row[tid];

    __shared__ float red[8];

    float m = fmaxf(fmaxf(v.x, v.y), fmaxf(v.z, v.w));
#pragma unroll
    for (int o = 16; o; o >>= 1) m = fmaxf(m, __shfl_xor_sync(0xffffffffu, m, o));
    if ((tid & 31) == 0) red[tid >> 5] = m;
    __syncthreads();
    float bm = fmaxf(fmaxf(fmaxf(red[0], red[1]), fmaxf(red[2], red[3])),
                     fmaxf(fmaxf(red[4], red[5]), fmaxf(red[6], red[7])));
    __syncthreads();

    v.x = __expf(v.x - bm); v.y = __expf(v.y - bm);
    v.z = __expf(v.z - bm); v.w = __expf(v.w - bm);
    float s = v.x + v.y + v.z + v.w;
#pragma unroll
    for (int o = 16; o; o >>= 1) s += __shfl_xor_sync(0xffffffffu, s, o);
    if ((tid & 31) == 0) red[tid >> 5] = s;
    __syncthreads();
    float bs = red[0] + red[1] + red[2] + red[3]
             + red[4] + red[5] + red[6] + red[7];
    float inv = 1.0f / bs;
    v.x *= inv; v.y *= inv; v.z *= inv; v.w *= inv;
    row[tid] = v;
}

// ---------------------------------------------------------------------------
// Elementwise: c = a * b  (float4)
// ---------------------------------------------------------------------------
__global__ void __launch_bounds__(256)
mul_kernel(const float* __restrict__ a, const float* __restrict__ b,
           float* __restrict__ c)
{
    int idx = blockIdx.x * 256 + threadIdx.x;
    float4 av = ((const float4*)a)[idx];
    float4 bv = ((const float4*)b)[idx];
    float4 cv;
    cv.x = av.x * bv.x; cv.y = av.y * bv.y;
    cv.z = av.z * bv.z; cv.w = av.w * bv.w;
    ((float4*)c)[idx] = cv;
}

// ---------------------------------------------------------------------------
extern "C" void kernel_launch(void* const* d_in, const int* in_sizes, int n_in,
                              void* d_out, int out_size)
{
    (void)in_sizes; (void)n_in; (void)out_size;

    const float* s    = (const float*)d_in[0];
    const float* kin  = (const float*)d_in[1];
    const float* mask = (const float*)d_in[2];
    const float* bias = (const float*)d_in[3];
    const float* Wq   = (const float*)d_in[4];
    const float* bq   = (const float*)d_in[5];
    const float* Wk   = (const float*)d_in[6];
    const float* Wv   = (const float*)d_in[7];
    const float* Wg   = (const float*)d_in[8];
    const float* Wo   = (const float*)d_in[9];
    const float* Wz   = (const float*)d_in[10];
    float* out = (float*)d_out;

    float *q, *k, *v, *g, *o, *go, *z;
    cudaGetSymbolAddress((void**)&q,  g_q);
    cudaGetSymbolAddress((void**)&k,  g_k);
    cudaGetSymbolAddress((void**)&v,  g_v);
    cudaGetSymbolAddress((void**)&g,  g_g);
    cudaGetSymbolAddress((void**)&o,  g_o);
    cudaGetSymbolAddress((void**)&go, g_go);
    cudaGetSymbolAddress((void**)&z,  g_z);

    dim3 gp(8, 8, 1);
    // q = s @ Wq^T + bq
    sgemm_nt_128<<<gp, 256>>>(s, NN, 0, Wq, NN, 0, bq, nullptr, 0,
                              q, NN, 0, NN, 1.f, 0);
    // k = kin @ Wk^T
    sgemm_nt_128<<<gp, 256>>>(kin, NN, 0, Wk, NN, 0, nullptr, nullptr, 0,
                              k, NN, 0, NN, 1.f, 0);
    // v = kin @ Wv^T
    sgemm_nt_128<<<gp, 256>>>(kin, NN, 0, Wv, NN, 0, nullptr, nullptr, 0,
                              v, NN, 0, NN, 1.f, 0);
    // g = sigmoid(s @ Wg^T)
    sgemm_nt_128<<<gp, 256>>>(s, NN, 0, Wg, NN, 0, nullptr, nullptr, 0,
                              g, NN, 0, NN, 1.f, 1);
    // z[h,i,j] = bias[i,j,:] @ Wz[:,h] + mask term
    zproj_kernel<<<(NN * NN) / 64, 128>>>(bias, Wz, mask, z);
    // logits = 0.125 * Qh @ Kh^T + z   (batched over 16 heads, in place)
    sgemm_nt_128<<<dim3(8, 8, HEADS), 256>>>(q, NN, HD, k, NN, HD,
                                             nullptr, z, (long long)NN * NN,
                                             z, NN, (long long)NN * NN,
                                             HD, 0.125f, 0);
    // softmax rows
    softmax_kernel<<<HEADS * NN, 256>>>(z);
    // O_h = P_h @ V_h
    sgemm_nn_128x64<<<dim3(1, 8, HEADS), 256>>>(z, NN, (long long)NN * NN,
                                                v, NN, HD,
                                                o, NN, HD, NN);
    // go = g * o
    mul_kernel<<<(NN * NN) / (256 * 4), 256>>>(g, o, go);
    // out = go @ Wo^T
    sgemm_nt_128<<<gp, 256>>>(go, NN, 0, Wo, NN, 0, nullptr, nullptr, 0,
                              out, NN, 0, NN, 1.f, 0);
}

// round 3
// speedup vs baseline: 2.3606x; 2.3606x over previous
#include <cuda_runtime.h>
#include <cuda_bf16.h>
#include <cstdint>

// ---------------------------------------------------------------------------
// CrossAttention: B=1, I=J=1024, C_S=1024, H=16, D=64, C_Z=128
// Round 3: all heavy GEMMs on tensor cores via bf16 hi/lo split (3-term MMA,
// ~fp32 accuracy). mma.sync.m16n8k16 + ldmatrix, BM=128 BN=64 BK=32.
// ---------------------------------------------------------------------------

#define NN 1024
#define HEADS 16
#define HD 64
#define CZ 128

typedef __nv_bfloat16 bf16;
typedef __nv_bfloat162 bf162;

// ---------------- scratch (device globals; allocation forbidden) -----------
__device__ bf16 g_sh [NN * NN], g_sl [NN * NN];
__device__ bf16 g_kih[NN * NN], g_kil[NN * NN];
__device__ bf16 g_Wqh[NN * NN], g_Wql[NN * NN];
__device__ bf16 g_Wkh[NN * NN], g_Wkl[NN * NN];
__device__ bf16 g_Wvh[NN * NN], g_Wvl[NN * NN];
__device__ bf16 g_Wgh[NN * NN], g_Wgl[NN * NN];
__device__ bf16 g_Woh[NN * NN], g_Wol[NN * NN];
__device__ bf16 g_qh [NN * NN], g_ql [NN * NN];
__device__ bf16 g_kh [NN * NN], g_kl [NN * NN];
__device__ bf16 g_vth[NN * NN], g_vtl[NN * NN];   // transposed V: [c_s][j]
__device__ float g_g [NN * NN];
__device__ float g_z [HEADS * NN * NN];           // logits, 64 MB
__device__ bf16 g_ph [HEADS * NN * NN], g_pl[HEADS * NN * NN];  // probs hi/lo
__device__ float g_o [NN * NN];
__device__ bf16 g_goh[NN * NN], g_gol[NN * NN];

// ---------------------------------------------------------------------------
// helpers
// ---------------------------------------------------------------------------
__device__ __forceinline__ void bsplit(float v, bf16& h, bf16& l) {
    h = __float2bfloat16(v);
    l = __float2bfloat16(v - __bfloat162float(h));
}

__device__ __forceinline__ void ldsm4(uint32_t* r, const void* p) {
    uint32_t a = (uint32_t)__cvta_generic_to_shared(p);
    asm volatile("ldmatrix.sync.aligned.m8n8.x4.shared.b16 {%0,%1,%2,%3}, [%4];\n"
                 : "=r"(r[0]), "=r"(r[1]), "=r"(r[2]), "=r"(r[3]) : "r"(a));
}

__device__ __forceinline__ void mma16816(float* d, const uint32_t* a,
                                         uint32_t b0, uint32_t b1) {
    asm volatile(
        "mma.sync.aligned.m16n8k16.row.col.f32.bf16.bf16.f32 "
        "{%0,%1,%2,%3}, {%4,%5,%6,%7}, {%8,%9}, {%0,%1,%2,%3};\n"
        : "+f"(d[0]), "+f"(d[1]), "+f"(d[2]), "+f"(d[3])
        : "r"(a[0]), "r"(a[1]), "r"(a[2]), "r"(a[3]), "r"(b0), "r"(b1));
}

// ---------------------------------------------------------------------------
// fp32 -> bf16 hi/lo split, elementwise (float4 per thread)
// ---------------------------------------------------------------------------
__global__ void __launch_bounds__(256)
conv_split(const float* __restrict__ x, bf16* __restrict__ xh,
           bf16* __restrict__ xl)
{
    int idx = blockIdx.x * 256 + threadIdx.x;
    float4 v = ((const float4*)x)[idx];
    bf16 h0, h1, h2, h3, l0, l1, l2, l3;
    bsplit(v.x, h0, l0); bsplit(v.y, h1, l1);
    bsplit(v.z, h2, l2); bsplit(v.w, h3, l3);
    bf162* H = (bf162*)(xh + idx * 4);
    bf162* L = (bf162*)(xl + idx * 4);
    H[0] = bf162{h0, h1}; H[1] = bf162{h2, h3};
    L[0] = bf162{l0, l1}; L[1] = bf162{l2, l3};
}

// ---------------------------------------------------------------------------
// Split-bf16 tensor-core NT GEMM:
//   acc[m,n] = sum_k A[m,k]*B[n,k]   (A = Ah+Al, B = Bh+Bl, 3-term MMA)
//   out = alpha*acc (+bias[n]) (+Cin[m,n]) (+sigmoid)
// BM=128, BN=64, BK=32, 256 threads (8 warps as 4m x 2n, warp tile 32x32).
// mode: 0 = fp32 Cf;  1 = hi/lo (Oh,Ol) row-major;  2 = hi/lo transposed.
// Batched via blockIdx.z with element strides.
// ---------------------------------------------------------------------------
__global__ void __launch_bounds__(256)
bsgemm(const bf16* __restrict__ Ah, const bf16* __restrict__ Al,
       int lda, long long bsA,
       const bf16* __restrict__ Bh, const bf16* __restrict__ Bl,
       int ldb, long long bsB,
       const float* __restrict__ bias,
       const float* __restrict__ Cin, long long bsCin,
       float* __restrict__ Cf, bf16* __restrict__ Oh, bf16* __restrict__ Ol,
       int ldc, long long bsC,
       int K, float alpha, int mode, int act)
{
    __shared__ __align__(16) bf16 As[2][2][128][24];  // [khalf][hl][row][pad]
    __shared__ __align__(16) bf16 Bs[2][2][64][24];

    const int tid = threadIdx.x;
    const int lane = tid & 31;
    const int warp = tid >> 5;
    const int wm = warp & 3;            // 0..3 -> m offset 32*wm
    const int wn = warp >> 2;           // 0..1 -> n offset 32*wn
    const int bx = blockIdx.x, by = blockIdx.y, bz = blockIdx.z;

    const bf16* Abh = Ah + bz * bsA + (long long)by * 128 * lda;
    const bf16* Abl = Al + bz * bsA + (long long)by * 128 * lda;
    const bf16* Bbh = Bh + bz * bsB + (long long)bx * 64 * ldb;
    const bf16* Bbl = Bl + bz * bsB + (long long)bx * 64 * ldb;

    float d[2][4][4];
#pragma unroll
    for (int mt = 0; mt < 2; mt++)
#pragma unroll
        for (int nt = 0; nt < 4; nt++)
#pragma unroll
            for (int e = 0; e < 4; e++) d[mt][nt][e] = 0.f;

    const int arow0 = tid >> 2;          // A load: rows tid/4, tid/4+64
    const int akc   = tid & 3;           // k-chunk 0..3 (8 bf16 each)
    const int brow  = tid >> 2;          // B load rows 0..63
    const int ldsr  = lane & 15;         // ldmatrix row within 16
    const int ldsc  = (lane & 16) ? 8 : 0;

    for (int k0 = 0; k0 < K; k0 += 32) {
        // gmem -> smem
#pragma unroll
        for (int t = 0; t < 2; t++) {
            int r = arow0 + t * 64;
            const bf16* sh = Abh + (long long)r * lda + k0 + akc * 8;
            const bf16* sl = Abl + (long long)r * lda + k0 + akc * 8;
            *(uint4*)&As[akc >> 1][0][r][(akc & 1) * 8] = *(const uint4*)sh;
            *(uint4*)&As[akc >> 1][1][r][(akc & 1) * 8] = *(const uint4*)sl;
        }
        {
            const bf16* sh = Bbh + (long long)brow * ldb + k0 + akc * 8;
            const bf16* sl = Bbl + (long long)brow * ldb + k0 + akc * 8;
            *(uint4*)&Bs[akc >> 1][0][brow][(akc & 1) * 8] = *(const uint4*)sh;
            *(uint4*)&Bs[akc >> 1][1][brow][(akc & 1) * 8] = *(const uint4*)sl;
        }
        __syncthreads();

#pragma unroll
        for (int kh = 0; kh < 2; kh++) {
            uint32_t ah[2][4], al[2][4], bh[2][4], bl[2][4];
#pragma unroll
            for (int mt = 0; mt < 2; mt++) {
                int r = wm * 32 + mt * 16 + ldsr;
                ldsm4(ah[mt], &As[kh][0][r][ldsc]);
                ldsm4(al[mt], &As[kh][1][r][ldsc]);
            }
#pragma unroll
            for (int np = 0; np < 2; np++) {
                int r = wn * 32 + np * 16 + ldsr;
                ldsm4(bh[np], &Bs[kh][0][r][ldsc]);
                ldsm4(bl[np], &Bs[kh][1][r][ldsc]);
            }
#pragma unroll
            for (int mt = 0; mt < 2; mt++)
#pragma unroll
                for (int nt = 0; nt < 4; nt++) {
                    int np = nt >> 1, sel = nt & 1;
                    uint32_t bh0 = bh[np][sel], bh1 = bh[np][sel + 2];
                    uint32_t bl0 = bl[np][sel], bl1 = bl[np][sel + 2];
                    mma16816(d[mt][nt], ah[mt], bh0, bh1);   // hi*hi
                    mma16816(d[mt][nt], ah[mt], bl0, bl1);   // hi*lo
                    mma16816(d[mt][nt], al[mt], bh0, bh1);   // lo*hi
                }
        }
        __syncthreads();
    }

    // epilogue
    const int g = lane >> 2, tig = lane & 3;
    const float* CinB = Cin ? (Cin + bz * bsCin) : nullptr;

#pragma unroll
    for (int mt = 0; mt < 2; mt++) {
#pragma unroll
        for (int nt = 0; nt < 4; nt++) {
            int c = bx * 64 + wn * 32 + nt * 8 + tig * 2;
#pragma unroll
            for (int half = 0; half < 2; half++) {
                int r = by * 128 + wm * 32 + mt * 16 + g + half * 8;
                float v0 = alpha * d[mt][nt][half * 2 + 0];
                float v1 = alpha * d[mt][nt][half * 2 + 1];
                if (CinB) {
                    float2 ci = *(const float2*)(CinB + (long long)r * ldc + c);
                    v0 += ci.x; v1 += ci.y;
                }
                if (bias) { v0 += bias[c]; v1 += bias[c + 1]; }
                if (act == 1) {
                    v0 = 1.f / (1.f + __expf(-v0));
                    v1 = 1.f / (1.f + __expf(-v1));
                }
                if (mode == 0) {
                    float2 ov = {v0, v1};
                    *(float2*)(Cf + bz * bsC + (long long)r * ldc + c) = ov;
                } else if (mode == 1) {
                    bf16 h0, h1, l0, l1;
                    bsplit(v0, h0, l0); bsplit(v1, h1, l1);
                    *(bf162*)(Oh + bz * bsC + (long long)r * ldc + c) = bf162{h0, h1};
                    *(bf162*)(Ol + bz * bsC + (long long)r * ldc + c) = bf162{l0, l1};
                } else {  // transposed [n][m]
                    bf16 h0, h1, l0, l1;
                    bsplit(v0, h0, l0); bsplit(v1, h1, l1);
                    Oh[bz * bsC + (long long)c * ldc + r]       = h0;
                    Oh[bz * bsC + (long long)(c + 1) * ldc + r] = h1;
                    Ol[bz * bsC + (long long)c * ldc + r]       = l0;
                    Ol[bz * bsC + (long long)(c + 1) * ldc + r] = l1;
                }
            }
        }
    }
}

// ---------------------------------------------------------------------------
// z projection: z[h, p] = sum_c bias[p, c] * Wz[c, h] + (1-mask[j])*(-1e6)
// ---------------------------------------------------------------------------
__global__ void __launch_bounds__(128)
zproj_kernel(const float* __restrict__ bias, const float* __restrict__ Wz,
             const float* __restrict__ mask, float* __restrict__ z)
{
    __shared__ float bs[64][129];
    __shared__ float wzs[128][16];

    const int tid = threadIdx.x;
    const long long p0 = (long long)blockIdx.x * 64;

    for (int e = tid; e < CZ * HEADS; e += 128)
        wzs[e >> 4][e & 15] = Wz[e];

    const int c4 = tid & 31;
    const int r0 = tid >> 5;
#pragma unroll
    for (int r = r0; r < 64; r += 4) {
        float4 v = *(const float4*)(bias + (p0 + r) * CZ + c4 * 4);
        bs[r][c4 * 4 + 0] = v.x;
        bs[r][c4 * 4 + 1] = v.y;
        bs[r][c4 * 4 + 2] = v.z;
        bs[r][c4 * 4 + 3] = v.w;
    }
    __syncthreads();

    const int pair = tid & 63;
    const int hh = (tid >> 6) * 8;

    float acc[8];
#pragma unroll
    for (int h = 0; h < 8; h++) acc[h] = 0.f;

#pragma unroll 8
    for (int c = 0; c < CZ; c++) {
        float bv = bs[pair][c];
        float4 w0 = *(const float4*)&wzs[c][hh];
        float4 w1 = *(const float4*)&wzs[c][hh + 4];
        acc[0] += bv * w0.x; acc[1] += bv * w0.y;
        acc[2] += bv * w0.z; acc[3] += bv * w0.w;
        acc[4] += bv * w1.x; acc[5] += bv * w1.y;
        acc[6] += bv * w1.z; acc[7] += bv * w1.w;
    }

    const long long p = p0 + pair;
    const int j = (int)(p & (NN - 1));
    const float madd = (1.0f - mask[j]) * (-1000000.0f);
#pragma unroll
    for (int h = 0; h < 8; h++)
        z[(long long)(hh + h) * (NN * NN) + p] = acc[h] + madd;
}

// ---------------------------------------------------------------------------
// Row softmax (rows of 1024) -> probs written as bf16 hi/lo
// ---------------------------------------------------------------------------
__global__ void __launch_bounds__(256)
softmax_kernel(const float* __restrict__ z, bf16* __restrict__ ph,
               bf16* __restrict__ pl)
{
    const long long rb = (long long)blockIdx.x * NN;
    const float4* row = (const float4*)(z + rb);
    const int tid = threadIdx.x;
    float4 v = row[tid];

    __shared__ float red[8];

    float m = fmaxf(fmaxf(v.x, v.y), fmaxf(v.z, v.w));
#pragma unroll
    for (int o = 16; o; o >>= 1) m = fmaxf(m, __shfl_xor_sync(0xffffffffu, m, o));
    if ((tid & 31) == 0) red[tid >> 5] = m;
    __syncthreads();
    float bm = fmaxf(fmaxf(fmaxf(red[0], red[1]), fmaxf(red[2], red[3])),
                     fmaxf(fmaxf(red[4], red[5]), fmaxf(red[6], red[7])));
    __syncthreads();

    v.x = __expf(v.x - bm); v.y = __expf(v.y - bm);
    v.z = __expf(v.z - bm); v.w = __expf(v.w - bm);
    float s = v.x + v.y + v.z + v.w;
#pragma unroll
    for (int o = 16; o; o >>= 1) s += __shfl_xor_sync(0xffffffffu, s, o);
    if ((tid & 31) == 0) red[tid >> 5] = s;
    __syncthreads();
    float bs = red[0] + red[1] + red[2] + red[3]
             + red[4] + red[5] + red[6] + red[7];
    float inv = 1.0f / bs;
    v.x *= inv; v.y *= inv; v.z *= inv; v.w *= inv;

    bf16 h0, h1, h2, h3, l0, l1, l2, l3;
    bsplit(v.x, h0, l0); bsplit(v.y, h1, l1);
    bsplit(v.z, h2, l2); bsplit(v.w, h3, l3);
    bf162* H = (bf162*)(ph + rb + tid * 4);
    bf162* L = (bf162*)(pl + rb + tid * 4);
    H[0] = bf162{h0, h1}; H[1] = bf162{h2, h3};
    L[0] = bf162{l0, l1}; L[1] = bf162{l2, l3};
}

// ---------------------------------------------------------------------------
// go = g * o, written as bf16 hi/lo
// ---------------------------------------------------------------------------
__global__ void __launch_bounds__(256)
mul_split_kernel(const float* __restrict__ a, const float* __restrict__ b,
                 bf16* __restrict__ ch, bf16* __restrict__ cl)
{
    int idx = blockIdx.x * 256 + threadIdx.x;
    float4 av = ((const float4*)a)[idx];
    float4 bv = ((const float4*)b)[idx];
    float4 cv;
    cv.x = av.x * bv.x; cv.y = av.y * bv.y;
    cv.z = av.z * bv.z; cv.w = av.w * bv.w;
    bf16 h0, h1, h2, h3, l0, l1, l2, l3;
    bsplit(cv.x, h0, l0); bsplit(cv.y, h1, l1);
    bsplit(cv.z, h2, l2); bsplit(cv.w, h3, l3);
    bf162* H = (bf162*)(ch + idx * 4);
    bf162* L = (bf162*)(cl + idx * 4);
    H[0] = bf162{h0, h1}; H[1] = bf162{h2, h3};
    L[0] = bf162{l0, l1}; L[1] = bf162{l2, l3};
}

// ---------------------------------------------------------------------------
extern "C" void kernel_launch(void* const* d_in, const int* in_sizes, int n_in,
                              void* d_out, int out_size)
{
    (void)in_sizes; (void)n_in; (void)out_size;

    const float* s    = (const float*)d_in[0];
    const float* kin  = (const float*)d_in[1];
    const float* mask = (const float*)d_in[2];
    const float* bias = (const float*)d_in[3];
    const float* Wq   = (const float*)d_in[4];
    const float* bq   = (const float*)d_in[5];
    const float* Wk   = (const float*)d_in[6];
    const float* Wv   = (const float*)d_in[7];
    const float* Wg   = (const float*)d_in[8];
    const float* Wo   = (const float*)d_in[9];
    const float* Wz   = (const float*)d_in[10];
    float* out = (float*)d_out;

    bf16 *sh, *sl, *kih, *kil, *Wqh, *Wql, *Wkh, *Wkl, *Wvh, *Wvl;
    bf16 *Wgh, *Wgl, *Woh, *Wol, *qh, *ql, *kh, *kl, *vth, *vtl;
    bf16 *ph, *pl, *goh, *gol;
    float *gg, *z, *o;
    cudaGetSymbolAddress((void**)&sh,  g_sh);  cudaGetSymbolAddress((void**)&sl,  g_sl);
    cudaGetSymbolAddress((void**)&kih, g_kih); cudaGetSymbolAddress((void**)&kil, g_kil);
    cudaGetSymbolAddress((void**)&Wqh, g_Wqh); cudaGetSymbolAddress((void**)&Wql, g_Wql);
    cudaGetSymbolAddress((void**)&Wkh, g_Wkh); cudaGetSymbolAddress((void**)&Wkl, g_Wkl);
    cudaGetSymbolAddress((void**)&Wvh, g_Wvh); cudaGetSymbolAddress((void**)&Wvl, g_Wvl);
    cudaGetSymbolAddress((void**)&Wgh, g_Wgh); cudaGetSymbolAddress((void**)&Wgl, g_Wgl);
    cudaGetSymbolAddress((void**)&Woh, g_Woh); cudaGetSymbolAddress((void**)&Wol, g_Wol);
    cudaGetSymbolAddress((void**)&qh,  g_qh);  cudaGetSymbolAddress((void**)&ql,  g_ql);
    cudaGetSymbolAddress((void**)&kh,  g_kh);  cudaGetSymbolAddress((void**)&kl,  g_kl);
    cudaGetSymbolAddress((void**)&vth, g_vth); cudaGetSymbolAddress((void**)&vtl, g_vtl);
    cudaGetSymbolAddress((void**)&ph,  g_ph);  cudaGetSymbolAddress((void**)&pl,  g_pl);
    cudaGetSymbolAddress((void**)&goh, g_goh); cudaGetSymbolAddress((void**)&gol, g_gol);
    cudaGetSymbolAddress((void**)&gg,  g_g);
    cudaGetSymbolAddress((void**)&z,   g_z);
    cudaGetSymbolAddress((void**)&o,   g_o);

    const int CVB = (NN * NN) / (256 * 4);   // 1024 blocks
    conv_split<<<CVB, 256>>>(s,   sh,  sl);
    conv_split<<<CVB, 256>>>(kin, kih, kil);
    conv_split<<<CVB, 256>>>(Wq,  Wqh, Wql);
    conv_split<<<CVB, 256>>>(Wk,  Wkh, Wkl);
    conv_split<<<CVB, 256>>>(Wv,  Wvh, Wvl);
    conv_split<<<CVB, 256>>>(Wg,  Wgh, Wgl);
    conv_split<<<CVB, 256>>>(Wo,  Woh, Wol);

    const long long ZST = (long long)NN * NN;
    dim3 gsq(16, 8, 1);

    // q = s @ Wq^T + bq  -> hi/lo
    bsgemm<<<gsq, 256>>>(sh, sl, NN, 0, Wqh, Wql, NN, 0, bq,
                         nullptr, 0, nullptr, qh, ql, NN, 0,
                         NN, 1.f, 1, 0);
    // k = kin @ Wk^T -> hi/lo
    bsgemm<<<gsq, 256>>>(kih, kil, NN, 0, Wkh, Wkl, NN, 0, nullptr,
                         nullptr, 0, nullptr, kh, kl, NN, 0,
                         NN, 1.f, 1, 0);
    // vT = (kin @ Wv^T)^T -> hi/lo transposed [c_s][j]
    bsgemm<<<gsq, 256>>>(kih, kil, NN, 0, Wvh, Wvl, NN, 0, nullptr,
                         nullptr, 0, nullptr, vth, vtl, NN, 0,
                         NN, 1.f, 2, 0);
    // g = sigmoid(s @ Wg^T) -> fp32
    bsgemm<<<gsq, 256>>>(sh, sl, NN, 0, Wgh, Wgl, NN, 0, nullptr,
                         nullptr, 0, gg, nullptr, nullptr, NN, 0,
                         NN, 1.f, 0, 1);
    // z = bias @ Wz + mask
    zproj_kernel<<<(NN * NN) / 64, 128>>>(bias, Wz, mask, z);
    // logits = 0.125 * Qh @ Kh^T + z (in place over z; batched 16 heads)
    bsgemm<<<dim3(16, 8, HEADS), 256>>>(qh, ql, NN, HD, kh, kl, NN, HD,
                                        nullptr, z, ZST, z, nullptr, nullptr,
                                        NN, ZST, HD, 0.125f, 0, 0);
    // softmax -> probs hi/lo
    softmax_kernel<<<HEADS * NN, 256>>>(z, ph, pl);
    // O_h = P_h @ V_h  (NT against transposed V), fp32 out at col offset 64h
    bsgemm<<<dim3(1, 8, HEADS), 256>>>(ph, pl, NN, ZST, vth, vtl, NN,
                                       (long long)HD * NN,
                                       nullptr, nullptr, 0, o, nullptr, nullptr,
                                       NN, HD, NN, 1.f, 0, 0);
    // go = g * o -> hi/lo
    mul_split_kernel<<<CVB, 256>>>(gg, o, goh, gol);
    // out = go @ Wo^T -> fp32
    bsgemm<<<gsq, 256>>>(goh, gol, NN, 0, Woh, Wol, NN, 0, nullptr,
                         nullptr, 0, out, nullptr, nullptr, NN, 0,
                         NN, 1.f, 0, 0);
}